// round 8
// baseline (speedup 1.0000x reference)
#include <cuda_runtime.h>
#include <cuda_fp16.h>

#define NN 100000
#define NE 1600000
#define SBLK 98   // number of 1024-wide scan blocks

// ---------------- scratch (static __device__, no allocs) ----------------
struct Zeroed {
    int cnt[NN];        // hist counts
    int cur[NN];        // fill cursors
    float stats[256];   // layer1 sum/sumsq [0:128), layer2 [128:256)
};
__device__ Zeroed g_z;

__device__ __half g_h16[NN * 64];       // GEMM output (pre-aggregate), fp16
__device__ float  g_agg[NN * 64];       // aggregated output, fp32
__device__ int2   g_edges[NE];          // CSR payload: {src, __float_as_int(edge_norm)}
__device__ int    g_rowptr[NN + 1];
__device__ float  g_dis[NN];
__device__ float  g_selfnorm[NN];
__device__ int    g_bsum[128];

// ---------------- helpers ----------------
__device__ __forceinline__ unsigned f2tf32(float x) {
    unsigned r;
    asm("cvt.rna.tf32.f32 %0, %1;" : "=r"(r) : "f"(x));
    return r;
}

__device__ __forceinline__ void mma_tf32(float* d, const unsigned* a, const unsigned* b) {
    asm volatile(
        "mma.sync.aligned.m16n8k8.row.col.f32.tf32.tf32.f32 "
        "{%0,%1,%2,%3}, {%4,%5,%6,%7}, {%8,%9}, {%0,%1,%2,%3};"
        : "+f"(d[0]), "+f"(d[1]), "+f"(d[2]), "+f"(d[3])
        : "r"(a[0]), "r"(a[1]), "r"(a[2]), "r"(a[3]), "r"(b[0]), "r"(b[1]));
}

__device__ __forceinline__ void cp16(void* smem, const void* gmem) {
    unsigned s = (unsigned)__cvta_generic_to_shared(smem);
    asm volatile("cp.async.ca.shared.global [%0], [%1], 16;" :: "r"(s), "l"(gmem));
}

// per-block int64-layout detect (node ids < 2^31: int64 => odd words all zero)
__device__ __forceinline__ int block_is64(const void* ei) {
    __shared__ int s_is64;
    if (threadIdx.x < 32) {
        const int* p = (const int*)ei;
        int nz = p[2 * threadIdx.x + 1] != 0;
        unsigned m = __ballot_sync(0xffffffffu, nz);
        if (threadIdx.x == 0) s_is64 = (m == 0);
    }
    __syncthreads();
    return s_is64;
}

// load edge-id pair [i, i+1] (i even) from either layout
__device__ __forceinline__ int2 edge_pair(const void* ei, int i, int is64) {
    if (is64) {
        longlong2 v = ((const longlong2*)ei)[i >> 1];
        return make_int2((int)v.x, (int)v.y);
    }
    return ((const int2*)ei)[i >> 1];
}

// ---------------- CSR build ----------------
__global__ void k_hist(const void* ei) {
    int is64 = block_is64(ei);
    int e = (blockIdx.x * blockDim.x + threadIdx.x) * 2;
    if (e >= NE) return;
    int2 d = edge_pair(ei, NE + e, is64);   // NE even => aligned pair
    atomicAdd(&g_z.cnt[d.x], 1);
    atomicAdd(&g_z.cnt[d.y], 1);
}

// shfl-based block scan (1024 threads, 3 syncs)
__global__ void k_scanA() {
    __shared__ int wsum[32];
    int t = threadIdx.x;
    int lane = t & 31;
    int wid = t >> 5;
    int gid = blockIdx.x * 1024 + t;
    int v = (gid < NN) ? g_z.cnt[gid] : 0;
    int x = v;
#pragma unroll
    for (int off = 1; off < 32; off <<= 1) {
        int y = __shfl_up_sync(0xffffffffu, x, off);
        if (lane >= off) x += y;
    }
    if (lane == 31) wsum[wid] = x;
    __syncthreads();
    if (wid == 0) {
        int s = wsum[lane];
#pragma unroll
        for (int off = 1; off < 32; off <<= 1) {
            int y = __shfl_up_sync(0xffffffffu, s, off);
            if (lane >= off) s += y;
        }
        wsum[lane] = s;
    }
    __syncthreads();
    int incl = x + (wid > 0 ? wsum[wid - 1] : 0);
    if (gid < NN) g_rowptr[gid] = incl - v;   // local exclusive
    if (t == 1023) g_bsum[blockIdx.x] = incl;
}

// every block redundantly scans the 98 block sums, then finalizes its 256 nodes
__global__ void k_scanB() {
    __shared__ int s[128];
    int t = threadIdx.x;
    int v = 0;
    if (t < 128) { v = (t < SBLK) ? g_bsum[t] : 0; s[t] = v; }
    __syncthreads();
#pragma unroll
    for (int off = 1; off < 128; off <<= 1) {
        int x = (t >= off && t < 128) ? s[t - off] : 0;
        __syncthreads();
        if (t < 128) s[t] += x;
        __syncthreads();
    }
    if (t < 128) s[t] -= v;                   // exclusive
    __syncthreads();
    int gid = blockIdx.x * blockDim.x + t;
    if (gid < NN) {
        g_rowptr[gid] += s[gid >> 10];
        float deg = (float)g_z.cnt[gid] + 1.0f;
        g_dis[gid] = rsqrtf(deg);
        g_selfnorm[gid] = 1.0f / deg;
    }
    if (gid == 0) g_rowptr[NN] = NE;
}

__global__ void k_fill(const void* ei) {
    int is64 = block_is64(ei);
    int e = (blockIdx.x * blockDim.x + threadIdx.x) * 2;
    if (e >= NE) return;
    int2 sp = edge_pair(ei, e, is64);
    int2 dp = edge_pair(ei, NE + e, is64);
    int pos0 = g_rowptr[dp.x] + atomicAdd(&g_z.cur[dp.x], 1);
    g_edges[pos0] = make_int2(sp.x, __float_as_int(g_dis[sp.x] * g_dis[dp.x]));
    int pos1 = g_rowptr[dp.y] + atomicAdd(&g_z.cur[dp.y], 1);
    g_edges[pos1] = make_int2(sp.y, __float_as_int(g_dis[sp.y] * g_dis[dp.y]));
}

// ---------------- tf32 MMA GEMM, 16-k staged cp.async pipeline ----------------
// out = act(A) @ W + bias, fp16 out. N = NT*8. Block: one 128-row tile, 256 threads.
// W read COALESCED (float4) and scattered into fragment layout in smem.
template <int K, int NT, int BN, int STAGES>
__global__ __launch_bounds__(256) void k_gemm(const float* __restrict__ A,
                                              const float* __restrict__ W,
                                              const float* __restrict__ bias,
                                              __half* __restrict__ out,
                                              const float* __restrict__ gamma,
                                              const float* __restrict__ beta,
                                              int soff) {
    constexpr int N = NT * 8;
    constexpr int NK8 = K / 8;
    constexpr int NK16 = K / 16;
    constexpr int ASTRIDE = 20;
    constexpr int ASTAGE = 128 * ASTRIDE;      // floats per stage
    extern __shared__ __align__(16) char smem[];
    unsigned* Bp = (unsigned*)smem;                            // NK8*NT*64
    float* As = (float*)(smem + NK8 * NT * 64 * 4);            // STAGES*ASTAGE
    float* sA = As + STAGES * ASTAGE;
    float* sB = sA + 64;

    int tid = threadIdx.x;
    int lane = tid & 31;
    int warp = tid >> 5;

    // coalesced W read -> analytic scatter into exact B-fragment layout
    {
        const float4* Wv = (const float4*)W;
        for (int i = tid; i < K * N / 4; i += 256) {
            float4 w = Wv[i];
            int base = i * 4;
            int row = base / N;          // k index
            int col = base - row * N;    // n index (N % 4 == 0 -> same row)
            int ks = row >> 3;
            int r8 = row & 7;
            int slot = r8 >> 2;
            int lp = r8 & 3;
            unsigned* dst = &Bp[(ks * NT) * 64 + lp * 2 + slot];
#pragma unroll
            for (int j = 0; j < 4; j++) {
                int c = col + j;
                int l_hi = (c & 7) << 2;
                int t = c >> 3;
                dst[t * 64 + l_hi * 2] = f2tf32(((const float*)&w)[j]);
            }
        }
    }
    if (BN) {
        if (tid < 64) {
            float mu = g_z.stats[soff + tid] * (1.0f / NN);
            float var = g_z.stats[soff + 64 + tid] * (1.0f / NN) - mu * mu;
            float a = gamma[tid] * rsqrtf(var + 1e-5f);
            sA[tid] = a;
            sB[tid] = beta[tid] - mu * a;
        }
    }

    float acc[NT][4];
#pragma unroll
    for (int t = 0; t < NT; t++)
#pragma unroll
        for (int j = 0; j < 4; j++) acc[t][j] = 0.f;

    int m0 = blockIdx.x * 128;
    __syncthreads();   // Bp/sA/sB ready

    // stage issue: 512 16B-chunks per stage, 2 per thread
    auto issue = [&](int st, int ks16) {
#pragma unroll
        for (int i = 0; i < 2; i++) {
            int idx = tid + i * 256;
            int row = idx >> 2, c = idx & 3;
            int m = m0 + row;
            if (m > NN - 1) m = NN - 1;
            cp16(As + st * ASTAGE + row * ASTRIDE + c * 4,
                 A + (size_t)m * K + ks16 * 16 + c * 4);
        }
        asm volatile("cp.async.commit_group;");
    };

#pragma unroll
    for (int s = 0; s < STAGES - 1 && s < NK16; s++) issue(s, s);

    for (int ks16 = 0; ks16 < NK16; ks16++) {
        asm volatile("cp.async.wait_group %0;" :: "n"(STAGES - 2));
        __syncthreads();
        int nxt = ks16 + STAGES - 1;
        if (nxt < NK16) issue(nxt % STAGES, nxt);

        const float* as = As + (ks16 % STAGES) * ASTAGE;
        int r = warp * 16 + (lane >> 2);
        int cc = lane & 3;
#pragma unroll
        for (int s = 0; s < 2; s++) {          // two k8 substeps
            int off = s * 8;
            float f0 = as[r * ASTRIDE + off + cc];
            float f1 = as[(r + 8) * ASTRIDE + off + cc];
            float f2 = as[r * ASTRIDE + off + cc + 4];
            float f3 = as[(r + 8) * ASTRIDE + off + cc + 4];
            if (BN) {
                int k = ks16 * 16 + off;
                float a0 = sA[k + cc], b0 = sB[k + cc];
                float a1 = sA[k + cc + 4], b1 = sB[k + cc + 4];
                f0 = fmaxf(fmaf(f0, a0, b0), 0.f);
                f1 = fmaxf(fmaf(f1, a0, b0), 0.f);
                f2 = fmaxf(fmaf(f2, a1, b1), 0.f);
                f3 = fmaxf(fmaf(f3, a1, b1), 0.f);
            }
            unsigned a[4] = { f2tf32(f0), f2tf32(f1), f2tf32(f2), f2tf32(f3) };
            const unsigned* bp = &Bp[(ks16 * 2 + s) * NT * 64 + lane * 2];
#pragma unroll
            for (int t = 0; t < NT; t++) {
                unsigned bb[2] = { bp[t * 64], bp[t * 64 + 1] };
                mma_tf32(acc[t], a, bb);
            }
        }
    }

    // epilogue: c0,c1 at (r, col..col+1); c2,c3 at (r+8, col..col+1); pack to half2
    int r0 = m0 + warp * 16 + (lane >> 2);
    int c0 = (lane & 3) * 2;
#pragma unroll
    for (int t = 0; t < NT; t++) {
        int col = t * 8 + c0;
        float2 bv = *(const float2*)(bias + col);
        if (r0 < NN) {
            __half2 o = __floats2half2_rn(acc[t][0] + bv.x, acc[t][1] + bv.y);
            *(__half2*)(out + (size_t)r0 * N + col) = o;
        }
        if (r0 + 8 < NN) {
            __half2 o = __floats2half2_rn(acc[t][2] + bv.x, acc[t][3] + bv.y);
            *(__half2*)(out + (size_t)(r0 + 8) * N + col) = o;
        }
    }
}

// ---------------- aggregate (+ fused BN stats): grid-stride warp-per-node ----------------
template <int C, int SOFF>
__global__ __launch_bounds__(256) void k_aggregate(const __half* __restrict__ h,
                                                   float* __restrict__ out) {
    constexpr int C2 = C / 2;
    int lane = threadIdx.x & 31;
    int wid = threadIdx.x >> 5;
    int warpG = blockIdx.x * 8 + wid;
    int nwarp = gridDim.x * 8;
    const __half2* h2 = (const __half2*)h;
    const bool act = (lane < C2);
    float ts0 = 0.f, ts1 = 0.f, tq0 = 0.f, tq1 = 0.f;

    for (int n = warpG; n < NN; n += nwarp) {
        int beg = g_rowptr[n];
        int end = g_rowptr[n + 1];
        float a0 = 0.f, a1 = 0.f;
        int e = beg;
        for (; e + 3 < end; e += 4) {       // 4-edge unroll for MLP
            int2 e0 = g_edges[e];
            int2 e1 = g_edges[e + 1];
            int2 e2 = g_edges[e + 2];
            int2 e3 = g_edges[e + 3];
            if (act) {
                float2 v0 = __half22float2(h2[(size_t)e0.x * C2 + lane]);
                float2 v1 = __half22float2(h2[(size_t)e1.x * C2 + lane]);
                float2 v2 = __half22float2(h2[(size_t)e2.x * C2 + lane]);
                float2 v3 = __half22float2(h2[(size_t)e3.x * C2 + lane]);
                float w0 = __int_as_float(e0.y), w1 = __int_as_float(e1.y);
                float w2 = __int_as_float(e2.y), w3 = __int_as_float(e3.y);
                a0 = fmaf(w0, v0.x, a0); a1 = fmaf(w0, v0.y, a1);
                a0 = fmaf(w1, v1.x, a0); a1 = fmaf(w1, v1.y, a1);
                a0 = fmaf(w2, v2.x, a0); a1 = fmaf(w2, v2.y, a1);
                a0 = fmaf(w3, v3.x, a0); a1 = fmaf(w3, v3.y, a1);
            }
        }
        for (; e < end; e++) {
            int2 ed = g_edges[e];
            if (act) {
                float w = __int_as_float(ed.y);
                float2 v = __half22float2(h2[(size_t)ed.x * C2 + lane]);
                a0 = fmaf(w, v.x, a0);
                a1 = fmaf(w, v.y, a1);
            }
        }
        if (act) {
            float sn = g_selfnorm[n];
            float2 vs = __half22float2(h2[(size_t)n * C2 + lane]);
            a0 = fmaf(sn, vs.x, a0);
            a1 = fmaf(sn, vs.y, a1);
            float2 o = { a0, a1 };
            *(float2*)(out + (size_t)n * C + 2 * lane) = o;
            if (SOFF >= 0) {
                ts0 += a0;
                ts1 += a1;
                tq0 = fmaf(a0, a0, tq0);
                tq1 = fmaf(a1, a1, tq1);
            }
        }
    }

    if (SOFF >= 0) {
        __shared__ float sm[4][256];
        sm[0][threadIdx.x] = ts0;
        sm[1][threadIdx.x] = ts1;
        sm[2][threadIdx.x] = tq0;
        sm[3][threadIdx.x] = tq1;
        __syncthreads();
        if (threadIdx.x < 32) {
            int l = threadIdx.x;
            float s0 = 0.f, s1 = 0.f, q0 = 0.f, q1 = 0.f;
#pragma unroll
            for (int w = 0; w < 8; w++) {
                s0 += sm[0][w * 32 + l];
                s1 += sm[1][w * 32 + l];
                q0 += sm[2][w * 32 + l];
                q1 += sm[3][w * 32 + l];
            }
            atomicAdd(&g_z.stats[SOFF + 2 * l], s0);
            atomicAdd(&g_z.stats[SOFF + 2 * l + 1], s1);
            atomicAdd(&g_z.stats[SOFF + 64 + 2 * l], q0);
            atomicAdd(&g_z.stats[SOFF + 64 + 2 * l + 1], q1);
        }
    }
}

// ---------------- launch ----------------
extern "C" void kernel_launch(void* const* d_in, const int* in_sizes, int n_in,
                              void* d_out, int out_size) {
    const float* x  = (const float*)d_in[0];
    const void*  ei = d_in[1];
    const float* W1 = (const float*)d_in[2];
    const float* b1 = (const float*)d_in[3];
    const float* g1 = (const float*)d_in[4];
    const float* be1 = (const float*)d_in[5];
    const float* W2 = (const float*)d_in[6];
    const float* b2 = (const float*)d_in[7];
    const float* g2 = (const float*)d_in[8];
    const float* be2 = (const float*)d_in[9];
    const float* W3 = (const float*)d_in[10];
    const float* b3 = (const float*)d_in[11];
    float* out = (float*)d_out;

    __half* h = nullptr;
    float* agg = nullptr;
    void* p_z = nullptr;
    cudaGetSymbolAddress((void**)&h, g_h16);
    cudaGetSymbolAddress((void**)&agg, g_agg);
    cudaGetSymbolAddress(&p_z, g_z);

    // dynamic smem sizes
    const int SM_G1 = 16 * 8 * 64 * 4 + 3 * 128 * 20 * 4 + 512;   // K=128,NT=8
    const int SM_G2 = 8 * 8 * 64 * 4 + 3 * 128 * 20 * 4 + 512;    // K=64, NT=8
    const int SM_G3 = 8 * 5 * 64 * 4 + 3 * 128 * 20 * 4 + 512;    // K=64, NT=5

    static cudaStream_t s2 = nullptr;
    static cudaEvent_t ev_fork = nullptr, ev_join = nullptr;
    if (!s2) {
        cudaStreamCreateWithFlags(&s2, cudaStreamNonBlocking);
        cudaEventCreateWithFlags(&ev_fork, cudaEventDisableTiming);
        cudaEventCreateWithFlags(&ev_join, cudaEventDisableTiming);
        cudaFuncSetAttribute(k_gemm<128, 8, 0, 3>,
                             cudaFuncAttributeMaxDynamicSharedMemorySize, SM_G1);
        cudaFuncSetAttribute(k_gemm<64, 8, 1, 3>,
                             cudaFuncAttributeMaxDynamicSharedMemorySize, SM_G2);
        cudaFuncSetAttribute(k_gemm<64, 5, 1, 3>,
                             cudaFuncAttributeMaxDynamicSharedMemorySize, SM_G3);
    }

    const int EB2 = (NE / 2 + 255) / 256;
    const int GB = (NN + 127) / 128;          // 782
    const int AGB = 1184;                     // grid-stride aggregate blocks

    cudaMemsetAsync(p_z, 0, sizeof(Zeroed));  // counters + cursors + stats
    cudaEventRecord(ev_fork, 0);              // fork point: GEMM1 can start at t=0
    cudaStreamWaitEvent(s2, ev_fork, 0);

    // CSR build on main stream (overlaps GEMM1)
    k_hist<<<EB2, 256>>>(ei);                                              // 1
    k_scanA<<<SBLK, 1024>>>();                                             // 2
    k_scanB<<<(NN + 255) / 256, 256>>>();                                  // 3
    // GEMM1 on s2, launched 4th so ncu profiles it (runs concurrently from t=0)
    k_gemm<128, 8, 0, 3><<<GB, 256, SM_G1, s2>>>(x, W1, b1, h, nullptr, nullptr, 0); // 4
    cudaEventRecord(ev_join, s2);
    k_fill<<<EB2, 256>>>(ei);                                              // 5

    // join, then the dependent chain
    cudaStreamWaitEvent(0, ev_join, 0);
    k_aggregate<64, 0><<<AGB, 256>>>(h, agg);                              // 6
    k_gemm<64, 8, 1, 3><<<GB, 256, SM_G2>>>(agg, W2, b2, h, g1, be1, 0);   // 7
    k_aggregate<64, 128><<<AGB, 256>>>(h, agg);                            // 8
    k_gemm<64, 5, 1, 3><<<GB, 256, SM_G3>>>(agg, W3, b3, h, g2, be2, 128); // 9
    k_aggregate<40, -1><<<AGB, 256>>>(h, out);                             // 10
}

// round 10
// speedup vs baseline: 1.0195x; 1.0195x over previous
#include <cuda_runtime.h>
#include <cuda_fp16.h>

#define NN 100000
#define NE 1600000
#define SBLK 98   // number of 1024-wide scan blocks

// ---------------- scratch (static __device__, no allocs) ----------------
struct Zeroed {
    int cnt[NN];        // hist counts
    int cur[NN];        // fill cursors
    float stats[256];   // layer1 sum/sumsq [0:128), layer2 [128:256)
};
__device__ Zeroed g_z;

__device__ __half g_h16[NN * 64];       // GEMM output (pre-aggregate), fp16
__device__ float  g_agg[NN * 64];       // aggregated output, fp32
__device__ int2   g_edges[NE];          // CSR payload: {src, __float_as_int(edge_norm)}
__device__ int    g_rowptr[NN + 1];
__device__ float  g_dis[NN];
__device__ float  g_selfnorm[NN];
__device__ int    g_bsum[128];

// ---------------- helpers ----------------
__device__ __forceinline__ unsigned f2tf32(float x) {
    unsigned r;
    asm("cvt.rna.tf32.f32 %0, %1;" : "=r"(r) : "f"(x));
    return r;
}

__device__ __forceinline__ void mma_tf32(float* d, const unsigned* a, const unsigned* b) {
    asm volatile(
        "mma.sync.aligned.m16n8k8.row.col.f32.tf32.tf32.f32 "
        "{%0,%1,%2,%3}, {%4,%5,%6,%7}, {%8,%9}, {%0,%1,%2,%3};"
        : "+f"(d[0]), "+f"(d[1]), "+f"(d[2]), "+f"(d[3])
        : "r"(a[0]), "r"(a[1]), "r"(a[2]), "r"(a[3]), "r"(b[0]), "r"(b[1]));
}

__device__ __forceinline__ void cp16(void* smem, const void* gmem) {
    unsigned s = (unsigned)__cvta_generic_to_shared(smem);
    asm volatile("cp.async.ca.shared.global [%0], [%1], 16;" :: "r"(s), "l"(gmem));
}

// per-block int64-layout detect (node ids < 2^31: int64 => odd words all zero)
__device__ __forceinline__ int block_is64(const void* ei) {
    __shared__ int s_is64;
    if (threadIdx.x < 32) {
        const int* p = (const int*)ei;
        int nz = p[2 * threadIdx.x + 1] != 0;
        unsigned m = __ballot_sync(0xffffffffu, nz);
        if (threadIdx.x == 0) s_is64 = (m == 0);
    }
    __syncthreads();
    return s_is64;
}

// load edge-id pair [i, i+1] (i even) from either layout
__device__ __forceinline__ int2 edge_pair(const void* ei, int i, int is64) {
    if (is64) {
        longlong2 v = ((const longlong2*)ei)[i >> 1];
        return make_int2((int)v.x, (int)v.y);
    }
    return ((const int2*)ei)[i >> 1];
}

// ---------------- CSR build ----------------
__global__ void k_hist(const void* ei) {
    int is64 = block_is64(ei);
    int e = (blockIdx.x * blockDim.x + threadIdx.x) * 2;
    if (e >= NE) return;
    int2 d = edge_pair(ei, NE + e, is64);   // NE even => aligned pair
    atomicAdd(&g_z.cnt[d.x], 1);
    atomicAdd(&g_z.cnt[d.y], 1);
}

// shfl-based block scan (1024 threads, 3 syncs)
__global__ void k_scanA() {
    __shared__ int wsum[32];
    int t = threadIdx.x;
    int lane = t & 31;
    int wid = t >> 5;
    int gid = blockIdx.x * 1024 + t;
    int v = (gid < NN) ? g_z.cnt[gid] : 0;
    int x = v;
#pragma unroll
    for (int off = 1; off < 32; off <<= 1) {
        int y = __shfl_up_sync(0xffffffffu, x, off);
        if (lane >= off) x += y;
    }
    if (lane == 31) wsum[wid] = x;
    __syncthreads();
    if (wid == 0) {
        int s = wsum[lane];
#pragma unroll
        for (int off = 1; off < 32; off <<= 1) {
            int y = __shfl_up_sync(0xffffffffu, s, off);
            if (lane >= off) s += y;
        }
        wsum[lane] = s;
    }
    __syncthreads();
    int incl = x + (wid > 0 ? wsum[wid - 1] : 0);
    if (gid < NN) g_rowptr[gid] = incl - v;   // local exclusive
    if (t == 1023) g_bsum[blockIdx.x] = incl;
}

// every block redundantly scans the 98 block sums, then finalizes its 256 nodes
__global__ void k_scanB() {
    __shared__ int s[128];
    int t = threadIdx.x;
    int v = 0;
    if (t < 128) { v = (t < SBLK) ? g_bsum[t] : 0; s[t] = v; }
    __syncthreads();
#pragma unroll
    for (int off = 1; off < 128; off <<= 1) {
        int x = (t >= off && t < 128) ? s[t - off] : 0;
        __syncthreads();
        if (t < 128) s[t] += x;
        __syncthreads();
    }
    if (t < 128) s[t] -= v;                   // exclusive
    __syncthreads();
    int gid = blockIdx.x * blockDim.x + t;
    if (gid < NN) {
        g_rowptr[gid] += s[gid >> 10];
        float deg = (float)g_z.cnt[gid] + 1.0f;
        g_dis[gid] = rsqrtf(deg);
        g_selfnorm[gid] = 1.0f / deg;
    }
    if (gid == 0) g_rowptr[NN] = NE;
}

__global__ void k_fill(const void* ei) {
    int is64 = block_is64(ei);
    int e = (blockIdx.x * blockDim.x + threadIdx.x) * 2;
    if (e >= NE) return;
    int2 sp = edge_pair(ei, e, is64);
    int2 dp = edge_pair(ei, NE + e, is64);
    int pos0 = g_rowptr[dp.x] + atomicAdd(&g_z.cur[dp.x], 1);
    g_edges[pos0] = make_int2(sp.x, __float_as_int(g_dis[sp.x] * g_dis[dp.x]));
    int pos1 = g_rowptr[dp.y] + atomicAdd(&g_z.cur[dp.y], 1);
    g_edges[pos1] = make_int2(sp.y, __float_as_int(g_dis[sp.y] * g_dis[dp.y]));
}

// ---------------- tf32 MMA GEMM: warp = 32 rows x 32 cols, B in registers ----------------
// out = act(A) @ W + bias, fp16 out. N = NT*8. Block: 128 rows, 256 threads (8 warps).
// Warp grid 4m x 2n. B fragments preloaded to registers per 64-k half.
// cp.async: commit EVERY iteration (unconditional) so wait_group(STAGES-2) at
// iteration g provably covers stage g — fixes the last-stage race.
template <int K, int NT, int BN, int STAGES>
__global__ __launch_bounds__(256) void k_gemm(const float* __restrict__ A,
                                              const float* __restrict__ W,
                                              const float* __restrict__ bias,
                                              __half* __restrict__ out,
                                              const float* __restrict__ gamma,
                                              const float* __restrict__ beta,
                                              int soff) {
    constexpr int N = NT * 8;
    constexpr int NK8 = K / 8;
    constexpr int NK16 = K / 16;
    constexpr int NHALF = K / 64;              // 64-k halves (1 or 2)
    constexpr int ASTRIDE = 20;
    constexpr int ASTAGE = 128 * ASTRIDE;      // floats per stage
    extern __shared__ __align__(16) char smem[];
    unsigned* Bp = (unsigned*)smem;                            // NK8*NT*64
    float* As = (float*)(smem + NK8 * NT * 64 * 4);            // STAGES*ASTAGE
    float* sA = As + STAGES * ASTAGE;
    float* sB = sA + 64;

    int tid = threadIdx.x;
    int lane = tid & 31;
    int warp = tid >> 5;
    int mw = warp & 3;         // m-warp: rows mw*32..mw*32+31
    int nw = warp >> 2;        // n-warp: tiles nw*4..nw*4+3

    // coalesced W read -> analytic scatter into exact B-fragment layout
    {
        const float4* Wv = (const float4*)W;
        for (int i = tid; i < K * N / 4; i += 256) {
            float4 w = Wv[i];
            int base = i * 4;
            int row = base / N;          // k index
            int col = base - row * N;    // n index (N % 4 == 0 -> same row)
            int ks = row >> 3;
            int r8 = row & 7;
            int slot = r8 >> 2;
            int lp = r8 & 3;
            unsigned* dst = &Bp[(ks * NT) * 64 + lp * 2 + slot];
#pragma unroll
            for (int j = 0; j < 4; j++) {
                int c = col + j;
                int l_hi = (c & 7) << 2;
                int t = c >> 3;
                dst[t * 64 + l_hi * 2] = f2tf32(((const float*)&w)[j]);
            }
        }
    }
    if (BN) {
        if (tid < 64) {
            float mu = g_z.stats[soff + tid] * (1.0f / NN);
            float var = g_z.stats[soff + 64 + tid] * (1.0f / NN) - mu * mu;
            float a = gamma[tid] * rsqrtf(var + 1e-5f);
            sA[tid] = a;
            sB[tid] = beta[tid] - mu * a;
        }
    }

    float acc[2][4][4];        // [mfrag][ntile][reg]
#pragma unroll
    for (int mf = 0; mf < 2; mf++)
#pragma unroll
        for (int j = 0; j < 4; j++)
#pragma unroll
            for (int q = 0; q < 4; q++) acc[mf][j][q] = 0.f;

    int m0 = blockIdx.x * 128;
    __syncthreads();   // Bp/sA/sB ready

    // stage loads: 512 16B-chunks per stage, 2 per thread (NO commit inside)
    auto issue = [&](int st, int ks16) {
#pragma unroll
        for (int i = 0; i < 2; i++) {
            int idx = tid + i * 256;
            int row = idx >> 2, c = idx & 3;
            int m = m0 + row;
            if (m > NN - 1) m = NN - 1;
            cp16(As + st * ASTAGE + row * ASTRIDE + c * 4,
                 A + (size_t)m * K + ks16 * 16 + c * 4);
        }
    };

#pragma unroll
    for (int s = 0; s < STAGES - 1 && s < NK16; s++) {
        issue(s, s);
        asm volatile("cp.async.commit_group;");
    }

    int r = mw * 32 + (lane >> 2);
    int cc = lane & 3;
    unsigned breg[8][4][2];    // [local kstep][ntile][reg]

#pragma unroll
    for (int h = 0; h < NHALF; h++) {
        // preload B fragments for this 64-k half into registers
#pragma unroll
        for (int ks = 0; ks < 8; ks++) {
#pragma unroll
            for (int j = 0; j < 4; j++) {
                int t = nw * 4 + j;
                if (t < NT) {
                    const unsigned* bp = &Bp[(h * 8 + ks) * NT * 64 + t * 64 + lane * 2];
                    breg[ks][j][0] = bp[0];
                    breg[ks][j][1] = bp[1];
                }
            }
        }

#pragma unroll
        for (int i = 0; i < 4; i++) {          // 4 ks16 steps per half
            int g = h * 4 + i;
            asm volatile("cp.async.wait_group %0;" :: "n"(STAGES - 2));
            __syncthreads();
            int nxt = g + STAGES - 1;
            if (nxt < NK16) issue(nxt % STAGES, nxt);
            asm volatile("cp.async.commit_group;");   // UNCONDITIONAL commit

            const float* as = As + (g % STAGES) * ASTAGE;
#pragma unroll
            for (int s = 0; s < 2; s++) {      // two k8 substeps
                int off = s * 8;
                int ksl = i * 2 + s;
#pragma unroll
                for (int mf = 0; mf < 2; mf++) {
                    int rr = r + mf * 16;
                    float f0 = as[rr * ASTRIDE + off + cc];
                    float f1 = as[(rr + 8) * ASTRIDE + off + cc];
                    float f2 = as[rr * ASTRIDE + off + cc + 4];
                    float f3 = as[(rr + 8) * ASTRIDE + off + cc + 4];
                    if (BN) {
                        int k = g * 16 + off;
                        float a0 = sA[k + cc], b0 = sB[k + cc];
                        float a1 = sA[k + cc + 4], b1 = sB[k + cc + 4];
                        f0 = fmaxf(fmaf(f0, a0, b0), 0.f);
                        f1 = fmaxf(fmaf(f1, a0, b0), 0.f);
                        f2 = fmaxf(fmaf(f2, a1, b1), 0.f);
                        f3 = fmaxf(fmaf(f3, a1, b1), 0.f);
                    }
                    unsigned a[4] = { f2tf32(f0), f2tf32(f1), f2tf32(f2), f2tf32(f3) };
#pragma unroll
                    for (int j = 0; j < 4; j++) {
                        if (nw * 4 + j < NT)
                            mma_tf32(acc[mf][j], a, breg[ksl][j]);
                    }
                }
            }
        }
    }

    // epilogue: c0,c1 at (r0, col..col+1); c2,c3 at (r0+8, col..col+1); pack to half2
    int c0 = (lane & 3) * 2;
#pragma unroll
    for (int mf = 0; mf < 2; mf++) {
        int r0 = m0 + mw * 32 + mf * 16 + (lane >> 2);
#pragma unroll
        for (int j = 0; j < 4; j++) {
            int t = nw * 4 + j;
            if (t < NT) {
                int col = t * 8 + c0;
                float2 bv = *(const float2*)(bias + col);
                if (r0 < NN) {
                    __half2 o = __floats2half2_rn(acc[mf][j][0] + bv.x, acc[mf][j][1] + bv.y);
                    *(__half2*)(out + (size_t)r0 * N + col) = o;
                }
                if (r0 + 8 < NN) {
                    __half2 o = __floats2half2_rn(acc[mf][j][2] + bv.x, acc[mf][j][3] + bv.y);
                    *(__half2*)(out + (size_t)(r0 + 8) * N + col) = o;
                }
            }
        }
    }
}

// ---------------- aggregate (+ fused BN stats): grid-stride warp-per-node ----------------
template <int C, int SOFF>
__global__ __launch_bounds__(256) void k_aggregate(const __half* __restrict__ h,
                                                   float* __restrict__ out) {
    constexpr int C2 = C / 2;
    int lane = threadIdx.x & 31;
    int wid = threadIdx.x >> 5;
    int warpG = blockIdx.x * 8 + wid;
    int nwarp = gridDim.x * 8;
    const __half2* h2 = (const __half2*)h;
    const bool act = (lane < C2);
    float ts0 = 0.f, ts1 = 0.f, tq0 = 0.f, tq1 = 0.f;

    for (int n = warpG; n < NN; n += nwarp) {
        int beg = g_rowptr[n];
        int end = g_rowptr[n + 1];
        float a0 = 0.f, a1 = 0.f;
        int e = beg;
        for (; e + 3 < end; e += 4) {       // 4-edge unroll for MLP
            int2 e0 = g_edges[e];
            int2 e1 = g_edges[e + 1];
            int2 e2 = g_edges[e + 2];
            int2 e3 = g_edges[e + 3];
            if (act) {
                float2 v0 = __half22float2(h2[(size_t)e0.x * C2 + lane]);
                float2 v1 = __half22float2(h2[(size_t)e1.x * C2 + lane]);
                float2 v2 = __half22float2(h2[(size_t)e2.x * C2 + lane]);
                float2 v3 = __half22float2(h2[(size_t)e3.x * C2 + lane]);
                float w0 = __int_as_float(e0.y), w1 = __int_as_float(e1.y);
                float w2 = __int_as_float(e2.y), w3 = __int_as_float(e3.y);
                a0 = fmaf(w0, v0.x, a0); a1 = fmaf(w0, v0.y, a1);
                a0 = fmaf(w1, v1.x, a0); a1 = fmaf(w1, v1.y, a1);
                a0 = fmaf(w2, v2.x, a0); a1 = fmaf(w2, v2.y, a1);
                a0 = fmaf(w3, v3.x, a0); a1 = fmaf(w3, v3.y, a1);
            }
        }
        for (; e < end; e++) {
            int2 ed = g_edges[e];
            if (act) {
                float w = __int_as_float(ed.y);
                float2 v = __half22float2(h2[(size_t)ed.x * C2 + lane]);
                a0 = fmaf(w, v.x, a0);
                a1 = fmaf(w, v.y, a1);
            }
        }
        if (act) {
            float sn = g_selfnorm[n];
            float2 vs = __half22float2(h2[(size_t)n * C2 + lane]);
            a0 = fmaf(sn, vs.x, a0);
            a1 = fmaf(sn, vs.y, a1);
            float2 o = { a0, a1 };
            *(float2*)(out + (size_t)n * C + 2 * lane) = o;
            if (SOFF >= 0) {
                ts0 += a0;
                ts1 += a1;
                tq0 = fmaf(a0, a0, tq0);
                tq1 = fmaf(a1, a1, tq1);
            }
        }
    }

    if (SOFF >= 0) {
        __shared__ float sm[4][256];
        sm[0][threadIdx.x] = ts0;
        sm[1][threadIdx.x] = ts1;
        sm[2][threadIdx.x] = tq0;
        sm[3][threadIdx.x] = tq1;
        __syncthreads();
        if (threadIdx.x < 32) {
            int l = threadIdx.x;
            float s0 = 0.f, s1 = 0.f, q0 = 0.f, q1 = 0.f;
#pragma unroll
            for (int w = 0; w < 8; w++) {
                s0 += sm[0][w * 32 + l];
                s1 += sm[1][w * 32 + l];
                q0 += sm[2][w * 32 + l];
                q1 += sm[3][w * 32 + l];
            }
            atomicAdd(&g_z.stats[SOFF + 2 * l], s0);
            atomicAdd(&g_z.stats[SOFF + 2 * l + 1], s1);
            atomicAdd(&g_z.stats[SOFF + 64 + 2 * l], q0);
            atomicAdd(&g_z.stats[SOFF + 64 + 2 * l + 1], q1);
        }
    }
}

// ---------------- launch ----------------
extern "C" void kernel_launch(void* const* d_in, const int* in_sizes, int n_in,
                              void* d_out, int out_size) {
    const float* x  = (const float*)d_in[0];
    const void*  ei = d_in[1];
    const float* W1 = (const float*)d_in[2];
    const float* b1 = (const float*)d_in[3];
    const float* g1 = (const float*)d_in[4];
    const float* be1 = (const float*)d_in[5];
    const float* W2 = (const float*)d_in[6];
    const float* b2 = (const float*)d_in[7];
    const float* g2 = (const float*)d_in[8];
    const float* be2 = (const float*)d_in[9];
    const float* W3 = (const float*)d_in[10];
    const float* b3 = (const float*)d_in[11];
    float* out = (float*)d_out;

    __half* h = nullptr;
    float* agg = nullptr;
    void* p_z = nullptr;
    cudaGetSymbolAddress((void**)&h, g_h16);
    cudaGetSymbolAddress((void**)&agg, g_agg);
    cudaGetSymbolAddress(&p_z, g_z);

    // dynamic smem sizes
    const int SM_G1 = 16 * 8 * 64 * 4 + 3 * 128 * 20 * 4 + 512;   // K=128,NT=8
    const int SM_G2 = 8 * 8 * 64 * 4 + 3 * 128 * 20 * 4 + 512;    // K=64, NT=8
    const int SM_G3 = 8 * 5 * 64 * 4 + 3 * 128 * 20 * 4 + 512;    // K=64, NT=5

    static cudaStream_t s2 = nullptr;
    static cudaEvent_t ev_fork = nullptr, ev_join = nullptr;
    if (!s2) {
        cudaStreamCreateWithFlags(&s2, cudaStreamNonBlocking);
        cudaEventCreateWithFlags(&ev_fork, cudaEventDisableTiming);
        cudaEventCreateWithFlags(&ev_join, cudaEventDisableTiming);
        cudaFuncSetAttribute(k_gemm<128, 8, 0, 3>,
                             cudaFuncAttributeMaxDynamicSharedMemorySize, SM_G1);
        cudaFuncSetAttribute(k_gemm<64, 8, 1, 3>,
                             cudaFuncAttributeMaxDynamicSharedMemorySize, SM_G2);
        cudaFuncSetAttribute(k_gemm<64, 5, 1, 3>,
                             cudaFuncAttributeMaxDynamicSharedMemorySize, SM_G3);
    }

    const int EB2 = (NE / 2 + 255) / 256;
    const int GB = (NN + 127) / 128;          // 782
    const int AGB = 1184;                     // grid-stride aggregate blocks

    cudaMemsetAsync(p_z, 0, sizeof(Zeroed));  // counters + cursors + stats

    // fork: GEMM1 captured FIRST so graph replay issues it at t=0
    cudaEventRecord(ev_fork, 0);
    cudaStreamWaitEvent(s2, ev_fork, 0);
    k_gemm<128, 8, 0, 3><<<GB, 256, SM_G1, s2>>>(x, W1, b1, h, nullptr, nullptr, 0);
    cudaEventRecord(ev_join, s2);

    // CSR build on main stream (overlaps GEMM1)
    k_hist<<<EB2, 256>>>(ei);
    k_scanA<<<SBLK, 1024>>>();
    k_scanB<<<(NN + 255) / 256, 256>>>();
    k_fill<<<EB2, 256>>>(ei);

    // join, then the dependent chain
    cudaStreamWaitEvent(0, ev_join, 0);
    k_aggregate<64, 0><<<AGB, 256>>>(h, agg);
    k_gemm<64, 8, 1, 3><<<GB, 256, SM_G2>>>(agg, W2, b2, h, g1, be1, 0);
    k_aggregate<64, 128><<<AGB, 256>>>(h, agg);
    k_gemm<64, 5, 1, 3><<<GB, 256, SM_G3>>>(agg, W3, b3, h, g2, be2, 128);
    k_aggregate<40, -1><<<AGB, 256>>>(h, out);
}

// round 11
// speedup vs baseline: 1.0556x; 1.0354x over previous
#include <cuda_runtime.h>
#include <cuda_fp16.h>

#define NN 100000
#define NE 1600000
#define SBLK 98   // number of 1024-wide scan blocks

// ---------------- scratch (static __device__, no allocs) ----------------
struct Zeroed {
    int cnt[NN];        // hist counts
    int cur[NN];        // fill cursors
    float stats[256];   // layer1 sum/sumsq [0:128), layer2 [128:256)
};
__device__ Zeroed g_z;

__device__ __half g_h16[NN * 64];       // GEMM output (pre-aggregate), fp16
__device__ float  g_agg[NN * 64];       // aggregated output, fp32
__device__ int2   g_edges[NE];          // CSR payload: {src, __float_as_int(edge_norm)}
__device__ int    g_rowloc[NN];         // block-local exclusive offsets (scanA)
__device__ int    g_rowptr[NN + 1];     // finalized rowptr (finrow; used by aggregates)
__device__ float  g_dis[NN];
__device__ float  g_selfnorm[NN];
__device__ int    g_bsum[128];

// ---------------- helpers ----------------
__device__ __forceinline__ unsigned f2tf32(float x) {
    unsigned r;
    asm("cvt.rna.tf32.f32 %0, %1;" : "=r"(r) : "f"(x));
    return r;
}

__device__ __forceinline__ void mma_tf32(float* d, const unsigned* a, const unsigned* b) {
    asm volatile(
        "mma.sync.aligned.m16n8k8.row.col.f32.tf32.tf32.f32 "
        "{%0,%1,%2,%3}, {%4,%5,%6,%7}, {%8,%9}, {%0,%1,%2,%3};"
        : "+f"(d[0]), "+f"(d[1]), "+f"(d[2]), "+f"(d[3])
        : "r"(a[0]), "r"(a[1]), "r"(a[2]), "r"(a[3]), "r"(b[0]), "r"(b[1]));
}

__device__ __forceinline__ void cp16(void* smem, const void* gmem) {
    unsigned s = (unsigned)__cvta_generic_to_shared(smem);
    asm volatile("cp.async.ca.shared.global [%0], [%1], 16;" :: "r"(s), "l"(gmem));
}

// per-block int64-layout detect (node ids < 2^31: int64 => odd words all zero)
__device__ __forceinline__ int block_is64(const void* ei) {
    __shared__ int s_is64;
    if (threadIdx.x < 32) {
        const int* p = (const int*)ei;
        int nz = p[2 * threadIdx.x + 1] != 0;
        unsigned m = __ballot_sync(0xffffffffu, nz);
        if (threadIdx.x == 0) s_is64 = (m == 0);
    }
    __syncthreads();
    return s_is64;
}

// load edge-id pair [i, i+1] (i even) from either layout
__device__ __forceinline__ int2 edge_pair(const void* ei, int i, int is64) {
    if (is64) {
        longlong2 v = ((const longlong2*)ei)[i >> 1];
        return make_int2((int)v.x, (int)v.y);
    }
    return ((const int2*)ei)[i >> 1];
}

// exclusive-prefix of the SBLK block sums into smem pref[] (needs >=128 threads)
__device__ __forceinline__ void smem_bsum_prefix(int* pref) {
    int t = threadIdx.x;
    int v = 0;
    if (t < 128) { v = (t < SBLK) ? g_bsum[t] : 0; pref[t] = v; }
    __syncthreads();
#pragma unroll
    for (int off = 1; off < 128; off <<= 1) {
        int x = (t >= off && t < 128) ? pref[t - off] : 0;
        __syncthreads();
        if (t < 128) pref[t] += x;
        __syncthreads();
    }
    if (t < 128) pref[t] -= v;    // exclusive
    __syncthreads();
}

// ---------------- CSR build ----------------
__global__ void k_hist(const void* ei) {
    int is64 = block_is64(ei);
    int e = (blockIdx.x * blockDim.x + threadIdx.x) * 2;
    if (e >= NE) return;
    int2 d = edge_pair(ei, NE + e, is64);   // NE even => aligned pair
    atomicAdd(&g_z.cnt[d.x], 1);
    atomicAdd(&g_z.cnt[d.y], 1);
}

// shfl-based block scan (1024 threads) + fused deg-init (dis/selfnorm from cnt)
__global__ void k_scanA() {
    __shared__ int wsum[32];
    int t = threadIdx.x;
    int lane = t & 31;
    int wid = t >> 5;
    int gid = blockIdx.x * 1024 + t;
    int v = (gid < NN) ? g_z.cnt[gid] : 0;
    int x = v;
#pragma unroll
    for (int off = 1; off < 32; off <<= 1) {
        int y = __shfl_up_sync(0xffffffffu, x, off);
        if (lane >= off) x += y;
    }
    if (lane == 31) wsum[wid] = x;
    __syncthreads();
    if (wid == 0) {
        int s = wsum[lane];
#pragma unroll
        for (int off = 1; off < 32; off <<= 1) {
            int y = __shfl_up_sync(0xffffffffu, s, off);
            if (lane >= off) s += y;
        }
        wsum[lane] = s;
    }
    __syncthreads();
    int incl = x + (wid > 0 ? wsum[wid - 1] : 0);
    if (gid < NN) {
        g_rowloc[gid] = incl - v;   // block-local exclusive
        float deg = (float)v + 1.0f;
        g_dis[gid] = rsqrtf(deg);
        g_selfnorm[gid] = 1.0f / deg;
    }
    if (t == 1023) g_bsum[blockIdx.x] = incl;
}

// finalize rowptr for the aggregates (runs CONCURRENT with k_fill on stream s3)
__global__ void k_finrow() {
    __shared__ int pref[128];
    smem_bsum_prefix(pref);
    int gid = blockIdx.x * blockDim.x + threadIdx.x;
    if (gid < NN) g_rowptr[gid] = g_rowloc[gid] + pref[gid >> 10];
    if (gid == 0) g_rowptr[NN] = NE;
}

// fill: computes global offsets inline (rowloc + smem bsum-prefix + cursor)
__global__ void k_fill(const void* ei) {
    __shared__ int pref[128];
    int is64 = block_is64(ei);
    smem_bsum_prefix(pref);
    int e = (blockIdx.x * blockDim.x + threadIdx.x) * 2;
    if (e >= NE) return;
    int2 sp = edge_pair(ei, e, is64);
    int2 dp = edge_pair(ei, NE + e, is64);
    int pos0 = g_rowloc[dp.x] + pref[dp.x >> 10] + atomicAdd(&g_z.cur[dp.x], 1);
    g_edges[pos0] = make_int2(sp.x, __float_as_int(g_dis[sp.x] * g_dis[dp.x]));
    int pos1 = g_rowloc[dp.y] + pref[dp.y >> 10] + atomicAdd(&g_z.cur[dp.y], 1);
    g_edges[pos1] = make_int2(sp.y, __float_as_int(g_dis[sp.y] * g_dis[dp.y]));
}

// ---------------- tf32 MMA GEMM: warp = 32 rows x 32 cols, B in registers ----------------
// (r10 passing version, unchanged: unconditional commit fixes the pipeline race)
template <int K, int NT, int BN, int STAGES>
__global__ __launch_bounds__(256) void k_gemm(const float* __restrict__ A,
                                              const float* __restrict__ W,
                                              const float* __restrict__ bias,
                                              __half* __restrict__ out,
                                              const float* __restrict__ gamma,
                                              const float* __restrict__ beta,
                                              int soff) {
    constexpr int N = NT * 8;
    constexpr int NK8 = K / 8;
    constexpr int NK16 = K / 16;
    constexpr int NHALF = K / 64;
    constexpr int ASTRIDE = 20;
    constexpr int ASTAGE = 128 * ASTRIDE;
    extern __shared__ __align__(16) char smem[];
    unsigned* Bp = (unsigned*)smem;                            // NK8*NT*64
    float* As = (float*)(smem + NK8 * NT * 64 * 4);            // STAGES*ASTAGE
    float* sA = As + STAGES * ASTAGE;
    float* sB = sA + 64;

    int tid = threadIdx.x;
    int lane = tid & 31;
    int warp = tid >> 5;
    int mw = warp & 3;
    int nw = warp >> 2;

    // coalesced W read -> analytic scatter into exact B-fragment layout
    {
        const float4* Wv = (const float4*)W;
        for (int i = tid; i < K * N / 4; i += 256) {
            float4 w = Wv[i];
            int base = i * 4;
            int row = base / N;
            int col = base - row * N;
            int ks = row >> 3;
            int r8 = row & 7;
            int slot = r8 >> 2;
            int lp = r8 & 3;
            unsigned* dst = &Bp[(ks * NT) * 64 + lp * 2 + slot];
#pragma unroll
            for (int j = 0; j < 4; j++) {
                int c = col + j;
                int l_hi = (c & 7) << 2;
                int t = c >> 3;
                dst[t * 64 + l_hi * 2] = f2tf32(((const float*)&w)[j]);
            }
        }
    }
    if (BN) {
        if (tid < 64) {
            float mu = g_z.stats[soff + tid] * (1.0f / NN);
            float var = g_z.stats[soff + 64 + tid] * (1.0f / NN) - mu * mu;
            float a = gamma[tid] * rsqrtf(var + 1e-5f);
            sA[tid] = a;
            sB[tid] = beta[tid] - mu * a;
        }
    }

    float acc[2][4][4];
#pragma unroll
    for (int mf = 0; mf < 2; mf++)
#pragma unroll
        for (int j = 0; j < 4; j++)
#pragma unroll
            for (int q = 0; q < 4; q++) acc[mf][j][q] = 0.f;

    int m0 = blockIdx.x * 128;
    __syncthreads();

    auto issue = [&](int st, int ks16) {
#pragma unroll
        for (int i = 0; i < 2; i++) {
            int idx = tid + i * 256;
            int row = idx >> 2, c = idx & 3;
            int m = m0 + row;
            if (m > NN - 1) m = NN - 1;
            cp16(As + st * ASTAGE + row * ASTRIDE + c * 4,
                 A + (size_t)m * K + ks16 * 16 + c * 4);
        }
    };

#pragma unroll
    for (int s = 0; s < STAGES - 1 && s < NK16; s++) {
        issue(s, s);
        asm volatile("cp.async.commit_group;");
    }

    int r = mw * 32 + (lane >> 2);
    int cc = lane & 3;
    unsigned breg[8][4][2];

#pragma unroll
    for (int h = 0; h < NHALF; h++) {
#pragma unroll
        for (int ks = 0; ks < 8; ks++) {
#pragma unroll
            for (int j = 0; j < 4; j++) {
                int t = nw * 4 + j;
                if (t < NT) {
                    const unsigned* bp = &Bp[(h * 8 + ks) * NT * 64 + t * 64 + lane * 2];
                    breg[ks][j][0] = bp[0];
                    breg[ks][j][1] = bp[1];
                }
            }
        }

#pragma unroll
        for (int i = 0; i < 4; i++) {
            int g = h * 4 + i;
            asm volatile("cp.async.wait_group %0;" :: "n"(STAGES - 2));
            __syncthreads();
            int nxt = g + STAGES - 1;
            if (nxt < NK16) issue(nxt % STAGES, nxt);
            asm volatile("cp.async.commit_group;");   // UNCONDITIONAL commit

            const float* as = As + (g % STAGES) * ASTAGE;
#pragma unroll
            for (int s = 0; s < 2; s++) {
                int off = s * 8;
                int ksl = i * 2 + s;
#pragma unroll
                for (int mf = 0; mf < 2; mf++) {
                    int rr = r + mf * 16;
                    float f0 = as[rr * ASTRIDE + off + cc];
                    float f1 = as[(rr + 8) * ASTRIDE + off + cc];
                    float f2 = as[rr * ASTRIDE + off + cc + 4];
                    float f3 = as[(rr + 8) * ASTRIDE + off + cc + 4];
                    if (BN) {
                        int k = g * 16 + off;
                        float a0 = sA[k + cc], b0 = sB[k + cc];
                        float a1 = sA[k + cc + 4], b1 = sB[k + cc + 4];
                        f0 = fmaxf(fmaf(f0, a0, b0), 0.f);
                        f1 = fmaxf(fmaf(f1, a0, b0), 0.f);
                        f2 = fmaxf(fmaf(f2, a1, b1), 0.f);
                        f3 = fmaxf(fmaf(f3, a1, b1), 0.f);
                    }
                    unsigned a[4] = { f2tf32(f0), f2tf32(f1), f2tf32(f2), f2tf32(f3) };
#pragma unroll
                    for (int j = 0; j < 4; j++) {
                        if (nw * 4 + j < NT)
                            mma_tf32(acc[mf][j], a, breg[ksl][j]);
                    }
                }
            }
        }
    }

    int c0 = (lane & 3) * 2;
#pragma unroll
    for (int mf = 0; mf < 2; mf++) {
        int r0 = m0 + mw * 32 + mf * 16 + (lane >> 2);
#pragma unroll
        for (int j = 0; j < 4; j++) {
            int t = nw * 4 + j;
            if (t < NT) {
                int col = t * 8 + c0;
                float2 bv = *(const float2*)(bias + col);
                if (r0 < NN) {
                    __half2 o = __floats2half2_rn(acc[mf][j][0] + bv.x, acc[mf][j][1] + bv.y);
                    *(__half2*)(out + (size_t)r0 * N + col) = o;
                }
                if (r0 + 8 < NN) {
                    __half2 o = __floats2half2_rn(acc[mf][j][2] + bv.x, acc[mf][j][3] + bv.y);
                    *(__half2*)(out + (size_t)(r0 + 8) * N + col) = o;
                }
            }
        }
    }
}

// ---------------- aggregate (+ fused BN stats): grid-stride warp-per-node ----------------
// 8-edge unroll (MLP 8) to probe/exploit latency-boundedness.
template <int C, int SOFF>
__global__ __launch_bounds__(256) void k_aggregate(const __half* __restrict__ h,
                                                   float* __restrict__ out) {
    constexpr int C2 = C / 2;
    int lane = threadIdx.x & 31;
    int wid = threadIdx.x >> 5;
    int warpG = blockIdx.x * 8 + wid;
    int nwarp = gridDim.x * 8;
    const __half2* h2 = (const __half2*)h;
    const bool act = (lane < C2);
    float ts0 = 0.f, ts1 = 0.f, tq0 = 0.f, tq1 = 0.f;

    for (int n = warpG; n < NN; n += nwarp) {
        int beg = g_rowptr[n];
        int end = g_rowptr[n + 1];
        float a0 = 0.f, a1 = 0.f;
        int e = beg;
        for (; e + 7 < end; e += 8) {       // 8-edge unroll
            int2 ed[8];
#pragma unroll
            for (int q = 0; q < 8; q++) ed[q] = g_edges[e + q];
            if (act) {
                float2 v[8];
#pragma unroll
                for (int q = 0; q < 8; q++)
                    v[q] = __half22float2(h2[(size_t)ed[q].x * C2 + lane]);
#pragma unroll
                for (int q = 0; q < 8; q++) {
                    float w = __int_as_float(ed[q].y);
                    a0 = fmaf(w, v[q].x, a0);
                    a1 = fmaf(w, v[q].y, a1);
                }
            }
        }
        for (; e + 3 < end; e += 4) {       // 4-edge group
            int2 ed[4];
#pragma unroll
            for (int q = 0; q < 4; q++) ed[q] = g_edges[e + q];
            if (act) {
                float2 v[4];
#pragma unroll
                for (int q = 0; q < 4; q++)
                    v[q] = __half22float2(h2[(size_t)ed[q].x * C2 + lane]);
#pragma unroll
                for (int q = 0; q < 4; q++) {
                    float w = __int_as_float(ed[q].y);
                    a0 = fmaf(w, v[q].x, a0);
                    a1 = fmaf(w, v[q].y, a1);
                }
            }
        }
        for (; e < end; e++) {
            int2 ed = g_edges[e];
            if (act) {
                float w = __int_as_float(ed.y);
                float2 v = __half22float2(h2[(size_t)ed.x * C2 + lane]);
                a0 = fmaf(w, v.x, a0);
                a1 = fmaf(w, v.y, a1);
            }
        }
        if (act) {
            float sn = g_selfnorm[n];
            float2 vs = __half22float2(h2[(size_t)n * C2 + lane]);
            a0 = fmaf(sn, vs.x, a0);
            a1 = fmaf(sn, vs.y, a1);
            float2 o = { a0, a1 };
            *(float2*)(out + (size_t)n * C + 2 * lane) = o;
            if (SOFF >= 0) {
                ts0 += a0;
                ts1 += a1;
                tq0 = fmaf(a0, a0, tq0);
                tq1 = fmaf(a1, a1, tq1);
            }
        }
    }

    if (SOFF >= 0) {
        __shared__ float sm[4][256];
        sm[0][threadIdx.x] = ts0;
        sm[1][threadIdx.x] = ts1;
        sm[2][threadIdx.x] = tq0;
        sm[3][threadIdx.x] = tq1;
        __syncthreads();
        if (threadIdx.x < 32) {
            int l = threadIdx.x;
            float s0 = 0.f, s1 = 0.f, q0 = 0.f, q1 = 0.f;
#pragma unroll
            for (int w = 0; w < 8; w++) {
                s0 += sm[0][w * 32 + l];
                s1 += sm[1][w * 32 + l];
                q0 += sm[2][w * 32 + l];
                q1 += sm[3][w * 32 + l];
            }
            atomicAdd(&g_z.stats[SOFF + 2 * l], s0);
            atomicAdd(&g_z.stats[SOFF + 2 * l + 1], s1);
            atomicAdd(&g_z.stats[SOFF + 64 + 2 * l], q0);
            atomicAdd(&g_z.stats[SOFF + 64 + 2 * l + 1], q1);
        }
    }
}

// ---------------- launch ----------------
extern "C" void kernel_launch(void* const* d_in, const int* in_sizes, int n_in,
                              void* d_out, int out_size) {
    const float* x  = (const float*)d_in[0];
    const void*  ei = d_in[1];
    const float* W1 = (const float*)d_in[2];
    const float* b1 = (const float*)d_in[3];
    const float* g1 = (const float*)d_in[4];
    const float* be1 = (const float*)d_in[5];
    const float* W2 = (const float*)d_in[6];
    const float* b2 = (const float*)d_in[7];
    const float* g2 = (const float*)d_in[8];
    const float* be2 = (const float*)d_in[9];
    const float* W3 = (const float*)d_in[10];
    const float* b3 = (const float*)d_in[11];
    float* out = (float*)d_out;

    __half* h = nullptr;
    float* agg = nullptr;
    void* p_z = nullptr;
    cudaGetSymbolAddress((void**)&h, g_h16);
    cudaGetSymbolAddress((void**)&agg, g_agg);
    cudaGetSymbolAddress(&p_z, g_z);

    // dynamic smem sizes
    const int SM_G1 = 16 * 8 * 64 * 4 + 3 * 128 * 20 * 4 + 512;   // K=128,NT=8
    const int SM_G2 = 8 * 8 * 64 * 4 + 3 * 128 * 20 * 4 + 512;    // K=64, NT=8
    const int SM_G3 = 8 * 5 * 64 * 4 + 3 * 128 * 20 * 4 + 512;    // K=64, NT=5

    static cudaStream_t s2 = nullptr, s3 = nullptr;
    static cudaEvent_t ev_fork = nullptr, ev_join = nullptr;
    static cudaEvent_t ev_scan = nullptr, ev_fin = nullptr;
    if (!s2) {
        cudaStreamCreateWithFlags(&s2, cudaStreamNonBlocking);
        cudaStreamCreateWithFlags(&s3, cudaStreamNonBlocking);
        cudaEventCreateWithFlags(&ev_fork, cudaEventDisableTiming);
        cudaEventCreateWithFlags(&ev_join, cudaEventDisableTiming);
        cudaEventCreateWithFlags(&ev_scan, cudaEventDisableTiming);
        cudaEventCreateWithFlags(&ev_fin, cudaEventDisableTiming);
        cudaFuncSetAttribute(k_gemm<128, 8, 0, 3>,
                             cudaFuncAttributeMaxDynamicSharedMemorySize, SM_G1);
        cudaFuncSetAttribute(k_gemm<64, 8, 1, 3>,
                             cudaFuncAttributeMaxDynamicSharedMemorySize, SM_G2);
        cudaFuncSetAttribute(k_gemm<64, 5, 1, 3>,
                             cudaFuncAttributeMaxDynamicSharedMemorySize, SM_G3);
    }

    const int EB2 = (NE / 2 + 255) / 256;
    const int GB = (NN + 127) / 128;          // 782
    const int AGB = 1184;                     // grid-stride aggregate blocks

    cudaMemsetAsync(p_z, 0, sizeof(Zeroed));  // counters + cursors + stats

    // fork: GEMM1 captured FIRST so graph replay issues it at t=0
    cudaEventRecord(ev_fork, 0);
    cudaStreamWaitEvent(s2, ev_fork, 0);
    k_gemm<128, 8, 0, 3><<<GB, 256, SM_G1, s2>>>(x, W1, b1, h, nullptr, nullptr, 0); // #1
    cudaEventRecord(ev_join, s2);

    // CSR build on main stream (overlaps GEMM1)
    k_hist<<<EB2, 256>>>(ei);                                              // #2
    k_scanA<<<SBLK, 1024>>>();                                             // #3
    cudaEventRecord(ev_scan, 0);
    k_fill<<<EB2, 256>>>(ei);                                              // #4 (profiled)
    // rowptr finalize concurrent with fill (only aggregates need it)
    cudaStreamWaitEvent(s3, ev_scan, 0);
    k_finrow<<<(NN + 255) / 256, 256, 0, s3>>>();                          // #5
    cudaEventRecord(ev_fin, s3);

    // join, then the dependent chain
    cudaStreamWaitEvent(0, ev_join, 0);
    cudaStreamWaitEvent(0, ev_fin, 0);
    k_aggregate<64, 0><<<AGB, 256>>>(h, agg);                              // #6
    k_gemm<64, 8, 1, 3><<<GB, 256, SM_G2>>>(agg, W2, b2, h, g1, be1, 0);   // #7
    k_aggregate<64, 128><<<AGB, 256>>>(h, agg);                            // #8
    k_gemm<64, 5, 1, 3><<<GB, 256, SM_G3>>>(agg, W3, b3, h, g2, be2, 128); // #9
    k_aggregate<40, -1><<<AGB, 256>>>(h, out);                             // #10
}

// round 12
// speedup vs baseline: 1.1686x; 1.1070x over previous
#include <cuda_runtime.h>
#include <cuda_fp16.h>

#define NN 100000
#define NE 1600000
#define SBLK 98   // number of 1024-wide scan blocks

// ---------------- scratch (static __device__, no allocs) ----------------
struct Zeroed {
    int cnt[NN];        // hist counts
    float stats[256];   // layer1 sum/sumsq [0:128), layer2 [128:256)
};
__device__ Zeroed g_z;

__device__ int    g_cur[NN];            // fill cursors (seeded by finrow, no memset)
__device__ __half g_h16[NN * 64];       // GEMM output rows pre-scaled by dis, fp16
__device__ float  g_agg[NN * 64];       // aggregated output, fp32
__device__ int    g_edgesrc[NE];        // CSR payload: src only (norm factored out)
__device__ int    g_rowloc[NN];         // block-local exclusive offsets (scanA)
__device__ int    g_rowptr[NN + 1];     // finalized rowptr
__device__ float  g_dis[NN];            // deg^-1/2
__device__ int    g_bsum[128];

// ---------------- helpers ----------------
__device__ __forceinline__ unsigned f2tf32(float x) {
    unsigned r;
    asm("cvt.rna.tf32.f32 %0, %1;" : "=r"(r) : "f"(x));
    return r;
}

__device__ __forceinline__ void mma_tf32(float* d, const unsigned* a, const unsigned* b) {
    asm volatile(
        "mma.sync.aligned.m16n8k8.row.col.f32.tf32.tf32.f32 "
        "{%0,%1,%2,%3}, {%4,%5,%6,%7}, {%8,%9}, {%0,%1,%2,%3};"
        : "+f"(d[0]), "+f"(d[1]), "+f"(d[2]), "+f"(d[3])
        : "r"(a[0]), "r"(a[1]), "r"(a[2]), "r"(a[3]), "r"(b[0]), "r"(b[1]));
}

__device__ __forceinline__ void cp16(void* smem, const void* gmem) {
    unsigned s = (unsigned)__cvta_generic_to_shared(smem);
    asm volatile("cp.async.ca.shared.global [%0], [%1], 16;" :: "r"(s), "l"(gmem));
}

// per-block int64-layout detect (node ids < 2^31: int64 => odd words all zero)
__device__ __forceinline__ int block_is64(const void* ei) {
    __shared__ int s_is64;
    if (threadIdx.x < 32) {
        const int* p = (const int*)ei;
        int nz = p[2 * threadIdx.x + 1] != 0;
        unsigned m = __ballot_sync(0xffffffffu, nz);
        if (threadIdx.x == 0) s_is64 = (m == 0);
    }
    __syncthreads();
    return s_is64;
}

// load edge-id pair [i, i+1] (i even) from either layout
__device__ __forceinline__ int2 edge_pair(const void* ei, int i, int is64) {
    if (is64) {
        longlong2 v = ((const longlong2*)ei)[i >> 1];
        return make_int2((int)v.x, (int)v.y);
    }
    return ((const int2*)ei)[i >> 1];
}

// exclusive-prefix of the SBLK block sums into smem pref[] (needs >=128 threads)
__device__ __forceinline__ void smem_bsum_prefix(int* pref) {
    int t = threadIdx.x;
    int v = 0;
    if (t < 128) { v = (t < SBLK) ? g_bsum[t] : 0; pref[t] = v; }
    __syncthreads();
#pragma unroll
    for (int off = 1; off < 128; off <<= 1) {
        int x = (t >= off && t < 128) ? pref[t - off] : 0;
        __syncthreads();
        if (t < 128) pref[t] += x;
        __syncthreads();
    }
    if (t < 128) pref[t] -= v;    // exclusive
    __syncthreads();
}

// ---------------- CSR build ----------------
__global__ void k_hist(const void* ei) {
    int is64 = block_is64(ei);
    int e = (blockIdx.x * blockDim.x + threadIdx.x) * 2;
    if (e >= NE) return;
    int2 d = edge_pair(ei, NE + e, is64);   // NE even => aligned pair
    atomicAdd(&g_z.cnt[d.x], 1);
    atomicAdd(&g_z.cnt[d.y], 1);
}

// shfl-based block scan (1024 threads) + fused deg-init (dis from cnt)
__global__ void k_scanA() {
    __shared__ int wsum[32];
    int t = threadIdx.x;
    int lane = t & 31;
    int wid = t >> 5;
    int gid = blockIdx.x * 1024 + t;
    int v = (gid < NN) ? g_z.cnt[gid] : 0;
    int x = v;
#pragma unroll
    for (int off = 1; off < 32; off <<= 1) {
        int y = __shfl_up_sync(0xffffffffu, x, off);
        if (lane >= off) x += y;
    }
    if (lane == 31) wsum[wid] = x;
    __syncthreads();
    if (wid == 0) {
        int s = wsum[lane];
#pragma unroll
        for (int off = 1; off < 32; off <<= 1) {
            int y = __shfl_up_sync(0xffffffffu, s, off);
            if (lane >= off) s += y;
        }
        wsum[lane] = s;
    }
    __syncthreads();
    int incl = x + (wid > 0 ? wsum[wid - 1] : 0);
    if (gid < NN) {
        g_rowloc[gid] = incl - v;   // block-local exclusive
        g_dis[gid] = rsqrtf((float)v + 1.0f);
    }
    if (t == 1023) g_bsum[blockIdx.x] = incl;
}

// finalize rowptr AND seed fill cursors (cur[n] = rowptr[n])
__global__ void k_finrow() {
    __shared__ int pref[128];
    smem_bsum_prefix(pref);
    int gid = blockIdx.x * blockDim.x + threadIdx.x;
    if (gid < NN) {
        int rp = g_rowloc[gid] + pref[gid >> 10];
        g_rowptr[gid] = rp;
        g_cur[gid] = rp;
    }
    if (gid == 0) g_rowptr[NN] = NE;
}

// fill: 2 scattered ops per edge (cursor atomic + 4B src store)
__global__ void k_fill(const void* ei) {
    int is64 = block_is64(ei);
    int e = (blockIdx.x * blockDim.x + threadIdx.x) * 2;
    if (e >= NE) return;
    int2 sp = edge_pair(ei, e, is64);
    int2 dp = edge_pair(ei, NE + e, is64);
    g_edgesrc[atomicAdd(&g_cur[dp.x], 1)] = sp.x;
    g_edgesrc[atomicAdd(&g_cur[dp.y], 1)] = sp.y;
}

// ---------------- tf32 MMA GEMM: warp = 32 rows x 32 cols, B in registers ----------------
// out[r] = dis[r] * (act(A[r]) @ W + bias), fp16 out (rows pre-scaled by D^-1/2).
template <int K, int NT, int BN, int STAGES>
__global__ __launch_bounds__(256) void k_gemm(const float* __restrict__ A,
                                              const float* __restrict__ W,
                                              const float* __restrict__ bias,
                                              __half* __restrict__ out,
                                              const float* __restrict__ gamma,
                                              const float* __restrict__ beta,
                                              int soff) {
    constexpr int N = NT * 8;
    constexpr int NK8 = K / 8;
    constexpr int NK16 = K / 16;
    constexpr int NHALF = K / 64;
    constexpr int ASTRIDE = 20;
    constexpr int ASTAGE = 128 * ASTRIDE;
    extern __shared__ __align__(16) char smem[];
    unsigned* Bp = (unsigned*)smem;                            // NK8*NT*64
    float* As = (float*)(smem + NK8 * NT * 64 * 4);            // STAGES*ASTAGE
    float* sA = As + STAGES * ASTAGE;
    float* sB = sA + 64;

    int tid = threadIdx.x;
    int lane = tid & 31;
    int warp = tid >> 5;
    int mw = warp & 3;
    int nw = warp >> 2;

    // coalesced W read -> analytic scatter into exact B-fragment layout
    {
        const float4* Wv = (const float4*)W;
        for (int i = tid; i < K * N / 4; i += 256) {
            float4 w = Wv[i];
            int base = i * 4;
            int row = base / N;
            int col = base - row * N;
            int ks = row >> 3;
            int r8 = row & 7;
            int slot = r8 >> 2;
            int lp = r8 & 3;
            unsigned* dst = &Bp[(ks * NT) * 64 + lp * 2 + slot];
#pragma unroll
            for (int j = 0; j < 4; j++) {
                int c = col + j;
                int l_hi = (c & 7) << 2;
                int t = c >> 3;
                dst[t * 64 + l_hi * 2] = f2tf32(((const float*)&w)[j]);
            }
        }
    }
    if (BN) {
        if (tid < 64) {
            float mu = g_z.stats[soff + tid] * (1.0f / NN);
            float var = g_z.stats[soff + 64 + tid] * (1.0f / NN) - mu * mu;
            float a = gamma[tid] * rsqrtf(var + 1e-5f);
            sA[tid] = a;
            sB[tid] = beta[tid] - mu * a;
        }
    }

    float acc[2][4][4];
#pragma unroll
    for (int mf = 0; mf < 2; mf++)
#pragma unroll
        for (int j = 0; j < 4; j++)
#pragma unroll
            for (int q = 0; q < 4; q++) acc[mf][j][q] = 0.f;

    int m0 = blockIdx.x * 128;
    __syncthreads();

    auto issue = [&](int st, int ks16) {
#pragma unroll
        for (int i = 0; i < 2; i++) {
            int idx = tid + i * 256;
            int row = idx >> 2, c = idx & 3;
            int m = m0 + row;
            if (m > NN - 1) m = NN - 1;
            cp16(As + st * ASTAGE + row * ASTRIDE + c * 4,
                 A + (size_t)m * K + ks16 * 16 + c * 4);
        }
    };

#pragma unroll
    for (int s = 0; s < STAGES - 1 && s < NK16; s++) {
        issue(s, s);
        asm volatile("cp.async.commit_group;");
    }

    int r = mw * 32 + (lane >> 2);
    int cc = lane & 3;
    unsigned breg[8][4][2];

#pragma unroll
    for (int h = 0; h < NHALF; h++) {
#pragma unroll
        for (int ks = 0; ks < 8; ks++) {
#pragma unroll
            for (int j = 0; j < 4; j++) {
                int t = nw * 4 + j;
                if (t < NT) {
                    const unsigned* bp = &Bp[(h * 8 + ks) * NT * 64 + t * 64 + lane * 2];
                    breg[ks][j][0] = bp[0];
                    breg[ks][j][1] = bp[1];
                }
            }
        }

#pragma unroll
        for (int i = 0; i < 4; i++) {
            int g = h * 4 + i;
            asm volatile("cp.async.wait_group %0;" :: "n"(STAGES - 2));
            __syncthreads();
            int nxt = g + STAGES - 1;
            if (nxt < NK16) issue(nxt % STAGES, nxt);
            asm volatile("cp.async.commit_group;");   // UNCONDITIONAL commit

            const float* as = As + (g % STAGES) * ASTAGE;
#pragma unroll
            for (int s = 0; s < 2; s++) {
                int off = s * 8;
                int ksl = i * 2 + s;
#pragma unroll
                for (int mf = 0; mf < 2; mf++) {
                    int rr = r + mf * 16;
                    float f0 = as[rr * ASTRIDE + off + cc];
                    float f1 = as[(rr + 8) * ASTRIDE + off + cc];
                    float f2 = as[rr * ASTRIDE + off + cc + 4];
                    float f3 = as[(rr + 8) * ASTRIDE + off + cc + 4];
                    if (BN) {
                        int k = g * 16 + off;
                        float a0 = sA[k + cc], b0 = sB[k + cc];
                        float a1 = sA[k + cc + 4], b1 = sB[k + cc + 4];
                        f0 = fmaxf(fmaf(f0, a0, b0), 0.f);
                        f1 = fmaxf(fmaf(f1, a0, b0), 0.f);
                        f2 = fmaxf(fmaf(f2, a1, b1), 0.f);
                        f3 = fmaxf(fmaf(f3, a1, b1), 0.f);
                    }
                    unsigned a[4] = { f2tf32(f0), f2tf32(f1), f2tf32(f2), f2tf32(f3) };
#pragma unroll
                    for (int j = 0; j < 4; j++) {
                        if (nw * 4 + j < NT)
                            mma_tf32(acc[mf][j], a, breg[ksl][j]);
                    }
                }
            }
        }
    }

    // epilogue: scale row by dis[r0], add bias, pack to half2
    int c0 = (lane & 3) * 2;
#pragma unroll
    for (int mf = 0; mf < 2; mf++) {
        int r0 = m0 + mw * 32 + mf * 16 + (lane >> 2);
        float d0 = (r0 < NN) ? g_dis[r0] : 0.f;
        float d1 = (r0 + 8 < NN) ? g_dis[r0 + 8] : 0.f;
#pragma unroll
        for (int j = 0; j < 4; j++) {
            int t = nw * 4 + j;
            if (t < NT) {
                int col = t * 8 + c0;
                float2 bv = *(const float2*)(bias + col);
                if (r0 < NN) {
                    __half2 o = __floats2half2_rn(d0 * (acc[mf][j][0] + bv.x),
                                                  d0 * (acc[mf][j][1] + bv.y));
                    *(__half2*)(out + (size_t)r0 * N + col) = o;
                }
                if (r0 + 8 < NN) {
                    __half2 o = __floats2half2_rn(d1 * (acc[mf][j][2] + bv.x),
                                                  d1 * (acc[mf][j][3] + bv.y));
                    *(__half2*)(out + (size_t)(r0 + 8) * N + col) = o;
                }
            }
        }
    }
}

// ---------------- aggregate (+ fused BN stats): grid-stride warp-per-node ----------------
// h rows pre-scaled by dis: out[n] = dis[n] * (sum_e h[src_e] + h[n])
template <int C, int SOFF>
__global__ __launch_bounds__(256) void k_aggregate(const __half* __restrict__ h,
                                                   float* __restrict__ out) {
    constexpr int C2 = C / 2;
    int lane = threadIdx.x & 31;
    int wid = threadIdx.x >> 5;
    int warpG = blockIdx.x * 8 + wid;
    int nwarp = gridDim.x * 8;
    const __half2* h2 = (const __half2*)h;
    const bool act = (lane < C2);
    float ts0 = 0.f, ts1 = 0.f, tq0 = 0.f, tq1 = 0.f;

    for (int n = warpG; n < NN; n += nwarp) {
        int beg = g_rowptr[n];
        int end = g_rowptr[n + 1];
        float a0 = 0.f, a1 = 0.f;
        int e = beg;
        for (; e + 7 < end; e += 8) {       // 8-edge unroll
            int sr[8];
#pragma unroll
            for (int q = 0; q < 8; q++) sr[q] = g_edgesrc[e + q];
            if (act) {
                float2 v[8];
#pragma unroll
                for (int q = 0; q < 8; q++)
                    v[q] = __half22float2(h2[(size_t)sr[q] * C2 + lane]);
#pragma unroll
                for (int q = 0; q < 8; q++) {
                    a0 += v[q].x;
                    a1 += v[q].y;
                }
            }
        }
        for (; e + 3 < end; e += 4) {       // 4-edge group
            int sr[4];
#pragma unroll
            for (int q = 0; q < 4; q++) sr[q] = g_edgesrc[e + q];
            if (act) {
                float2 v[4];
#pragma unroll
                for (int q = 0; q < 4; q++)
                    v[q] = __half22float2(h2[(size_t)sr[q] * C2 + lane]);
#pragma unroll
                for (int q = 0; q < 4; q++) {
                    a0 += v[q].x;
                    a1 += v[q].y;
                }
            }
        }
        for (; e < end; e++) {
            int sr = g_edgesrc[e];
            if (act) {
                float2 v = __half22float2(h2[(size_t)sr * C2 + lane]);
                a0 += v.x;
                a1 += v.y;
            }
        }
        if (act) {
            float2 vs = __half22float2(h2[(size_t)n * C2 + lane]);
            float dn = g_dis[n];
            a0 = dn * (a0 + vs.x);
            a1 = dn * (a1 + vs.y);
            float2 o = { a0, a1 };
            *(float2*)(out + (size_t)n * C + 2 * lane) = o;
            if (SOFF >= 0) {
                ts0 += a0;
                ts1 += a1;
                tq0 = fmaf(a0, a0, tq0);
                tq1 = fmaf(a1, a1, tq1);
            }
        }
    }

    if (SOFF >= 0) {
        __shared__ float sm[4][256];
        sm[0][threadIdx.x] = ts0;
        sm[1][threadIdx.x] = ts1;
        sm[2][threadIdx.x] = tq0;
        sm[3][threadIdx.x] = tq1;
        __syncthreads();
        if (threadIdx.x < 32) {
            int l = threadIdx.x;
            float s0 = 0.f, s1 = 0.f, q0 = 0.f, q1 = 0.f;
#pragma unroll
            for (int w = 0; w < 8; w++) {
                s0 += sm[0][w * 32 + l];
                s1 += sm[1][w * 32 + l];
                q0 += sm[2][w * 32 + l];
                q1 += sm[3][w * 32 + l];
            }
            atomicAdd(&g_z.stats[SOFF + 2 * l], s0);
            atomicAdd(&g_z.stats[SOFF + 2 * l + 1], s1);
            atomicAdd(&g_z.stats[SOFF + 64 + 2 * l], q0);
            atomicAdd(&g_z.stats[SOFF + 64 + 2 * l + 1], q1);
        }
    }
}

// ---------------- launch ----------------
extern "C" void kernel_launch(void* const* d_in, const int* in_sizes, int n_in,
                              void* d_out, int out_size) {
    const float* x  = (const float*)d_in[0];
    const void*  ei = d_in[1];
    const float* W1 = (const float*)d_in[2];
    const float* b1 = (const float*)d_in[3];
    const float* g1 = (const float*)d_in[4];
    const float* be1 = (const float*)d_in[5];
    const float* W2 = (const float*)d_in[6];
    const float* b2 = (const float*)d_in[7];
    const float* g2 = (const float*)d_in[8];
    const float* be2 = (const float*)d_in[9];
    const float* W3 = (const float*)d_in[10];
    const float* b3 = (const float*)d_in[11];
    float* out = (float*)d_out;

    __half* h = nullptr;
    float* agg = nullptr;
    void* p_z = nullptr;
    cudaGetSymbolAddress((void**)&h, g_h16);
    cudaGetSymbolAddress((void**)&agg, g_agg);
    cudaGetSymbolAddress(&p_z, g_z);

    // dynamic smem sizes
    const int SM_G1 = 16 * 8 * 64 * 4 + 3 * 128 * 20 * 4 + 512;   // K=128,NT=8
    const int SM_G2 = 8 * 8 * 64 * 4 + 3 * 128 * 20 * 4 + 512;    // K=64, NT=8
    const int SM_G3 = 8 * 5 * 64 * 4 + 3 * 128 * 20 * 4 + 512;    // K=64, NT=5

    static cudaStream_t s2 = nullptr;
    static cudaEvent_t ev_scan = nullptr, ev_join = nullptr;
    if (!s2) {
        cudaStreamCreateWithFlags(&s2, cudaStreamNonBlocking);
        cudaEventCreateWithFlags(&ev_scan, cudaEventDisableTiming);
        cudaEventCreateWithFlags(&ev_join, cudaEventDisableTiming);
        cudaFuncSetAttribute(k_gemm<128, 8, 0, 3>,
                             cudaFuncAttributeMaxDynamicSharedMemorySize, SM_G1);
        cudaFuncSetAttribute(k_gemm<64, 8, 1, 3>,
                             cudaFuncAttributeMaxDynamicSharedMemorySize, SM_G2);
        cudaFuncSetAttribute(k_gemm<64, 5, 1, 3>,
                             cudaFuncAttributeMaxDynamicSharedMemorySize, SM_G3);
    }

    const int EB2 = (NE / 2 + 255) / 256;
    const int GB = (NN + 127) / 128;          // 782
    const int AGB = 1184;                     // grid-stride aggregate blocks

    cudaMemsetAsync(p_z, 0, sizeof(Zeroed));  // hist counts + stats

    // CSR front on main stream
    k_hist<<<EB2, 256>>>(ei);                                              // #1
    k_scanA<<<SBLK, 1024>>>();                                             // #2 (writes dis)
    cudaEventRecord(ev_scan, 0);
    k_finrow<<<(NN + 255) / 256, 256>>>();                                 // #3 (rowptr + cursors)
    k_fill<<<EB2, 256>>>(ei);                                              // #4 (profiled)
    // GEMM1 forks after scanA (needs dis for row scaling); overlaps finrow+fill
    cudaStreamWaitEvent(s2, ev_scan, 0);
    k_gemm<128, 8, 0, 3><<<GB, 256, SM_G1, s2>>>(x, W1, b1, h, nullptr, nullptr, 0); // #5
    cudaEventRecord(ev_join, s2);

    // join, then the dependent chain
    cudaStreamWaitEvent(0, ev_join, 0);
    k_aggregate<64, 0><<<AGB, 256>>>(h, agg);                              // #6
    k_gemm<64, 8, 1, 3><<<GB, 256, SM_G2>>>(agg, W2, b2, h, g1, be1, 0);   // #7
    k_aggregate<64, 128><<<AGB, 256>>>(h, agg);                            // #8
    k_gemm<64, 5, 1, 3><<<GB, 256, SM_G3>>>(agg, W3, b3, h, g2, be2, 128); // #9
    k_aggregate<40, -1><<<AGB, 256>>>(h, out);                             // #10
}